// round 1
// baseline (speedup 1.0000x reference)
#include <cuda_runtime.h>

// Problem constants
#define NN   16384      // nodes (B*NPER)
#define EE   65536      // edges
#define HH   32         // hidden
#define BBAT 32         // batch
#define NPER 512
#define NLAY 4
#define KTOT 320        // 256 (c⊗x) + 32 (bias path) + 32 (root path)

// ---------------- scratch (static device globals; no allocs) ----------------
__device__ __align__(16) float g_xbuf[2][NN * HH];     // ping-pong node features (2x2MB)
__device__ __align__(16) float g_agg2[NN * 288];       // per-node accumulated outer products (18.9MB)
__device__ __align__(16) float g_B[NLAY * KTOT * HH];  // fused per-layer weight matrix (160KB)
__device__ int   g_deg[NN];
__device__ float g_invdeg[NN];
__device__ int   g_rowstart[NN + 1];
__device__ int   g_cursor[NN];
__device__ int   g_payload[EE];                        // (src<<4)|attr, grouped by dst

// ---------------- f32x2 helpers (Blackwell packed fp32) ----------------
__device__ __forceinline__ unsigned long long fma2(unsigned long long a,
                                                   unsigned long long b,
                                                   unsigned long long c) {
    unsigned long long d;
    asm("fma.rn.f32x2 %0, %1, %2, %3;" : "=l"(d) : "l"(a), "l"(b), "l"(c));
    return d;
}
__device__ __forceinline__ unsigned long long rep2(float a) {
    unsigned int u = __float_as_uint(a);
    unsigned long long d;
    asm("mov.b64 %0, {%1, %1};" : "=l"(d) : "r"(u));
    return d;
}
__device__ __forceinline__ float2 unpk(unsigned long long v) {
    unsigned int lo, hi;
    asm("mov.b64 {%0, %1}, %2;" : "=r"(lo), "=r"(hi) : "l"(v));
    return make_float2(__uint_as_float(lo), __uint_as_float(hi));
}

// ---------------- setup kernels ----------------

// x[n,h] = node_emb[x_nodes[n], h]; also zero degree counters
__global__ __launch_bounds__(256) void k_init(const int* __restrict__ xn,
                                              const float* __restrict__ nemb) {
    int i = blockIdx.x * 256 + threadIdx.x;   // < NN*HH
    int n = i >> 5, h = i & 31;
    g_xbuf[0][i] = nemb[xn[n] * HH + h];
    if (i < NN) g_deg[i] = 0;
}

// Build fused weight matrix B[l][k][o], k in [0,320):
//   k<256:   lin_w[l][k>>5][ (k&31)*32 + o ]
//   k<288:   lin_b[l][ (k-256)*32 + o ]
//   else:    root_w[l][ (k-288)*32 + o ]
__global__ __launch_bounds__(256) void k_prepB(const float* __restrict__ lin_w,
                                               const float* __restrict__ lin_b,
                                               const float* __restrict__ root_w) {
    int i = blockIdx.x * 256 + threadIdx.x;   // < NLAY*KTOT*HH
    int l = i / (KTOT * HH);
    int rem = i - l * KTOT * HH;
    int r = rem >> 5, o = rem & 31;
    float v;
    if (r < 256)      v = lin_w[l * 8192 + (r >> 5) * 1024 + (r & 31) * 32 + o];
    else if (r < 288) v = lin_b[l * 1024 + (r - 256) * 32 + o];
    else              v = root_w[l * 1024 + (r - 288) * 32 + o];
    g_B[i] = v;
}

__global__ __launch_bounds__(256) void k_count(const int* __restrict__ edge_index) {
    int e = blockIdx.x * 256 + threadIdx.x;   // < EE
    atomicAdd(&g_deg[edge_index[EE + e]], 1);
}

// single-block exclusive scan of degrees -> rowstart/cursor/invdeg
__global__ __launch_bounds__(1024) void k_scan() {
    __shared__ int sm[1024];
    int tid = threadIdx.x;
    int base = tid * 16;
    int loc[16];
    int s = 0;
#pragma unroll
    for (int t = 0; t < 16; t++) { loc[t] = g_deg[base + t]; s += loc[t]; }
    sm[tid] = s;
    __syncthreads();
    for (int off = 1; off < 1024; off <<= 1) {
        int v = (tid >= off) ? sm[tid - off] : 0;
        __syncthreads();
        sm[tid] += v;
        __syncthreads();
    }
    int run = sm[tid] - s;   // exclusive prefix
#pragma unroll
    for (int t = 0; t < 16; t++) {
        int idx = base + t;
        g_rowstart[idx] = run;
        g_cursor[idx]   = run;
        int d = loc[t] > 0 ? loc[t] : 1;
        g_invdeg[idx] = 1.0f / (float)d;
        run += loc[t];
    }
    if (tid == 1023) g_rowstart[NN] = run;
}

__global__ __launch_bounds__(256) void k_scatter(const int* __restrict__ edge_index,
                                                 const int* __restrict__ edge_attr) {
    int e = blockIdx.x * 256 + threadIdx.x;   // < EE
    int d = edge_index[EE + e];
    int pos = atomicAdd(&g_cursor[d], 1);
    g_payload[pos] = (edge_index[e] << 4) | edge_attr[e];
}

// ---------------- per-layer kernels ----------------

// Edge accumulation: warp per dst node, lane = feature i.
// acc[j] = sum over incoming edges of relu(edge_emb[l][attr])[j] * x[src][i]   (j<8)
// acc[8] = sum over incoming edges of x[src][i]                                (bias path)
// Writes AGG2[d, j*32+i] pre-scaled by 1/max(deg,1).
__global__ __launch_bounds__(256) void k_edge(const float* __restrict__ eemb,
                                              int inbuf, int l) {
    __shared__ float cs[128];
    if (threadIdx.x < 128) cs[threadIdx.x] = fmaxf(eemb[l * 128 + threadIdx.x], 0.0f);
    __syncthreads();

    int node = blockIdx.x * 8 + (threadIdx.x >> 5);
    int lane = threadIdx.x & 31;
    const float* __restrict__ xin = g_xbuf[inbuf];

    int beg = g_rowstart[node], end = g_rowstart[node + 1];
    float acc[9];
#pragma unroll
    for (int j = 0; j < 9; j++) acc[j] = 0.0f;

    for (int k = beg; k < end; k++) {
        int p = g_payload[k];
        float xv = __ldg(&xin[(p >> 4) * HH + lane]);
        const float* c = &cs[(p & 15) * 8];
#pragma unroll
        for (int j = 0; j < 8; j++) acc[j] = fmaf(c[j], xv, acc[j]);
        acc[8] += xv;
    }
    float inv = g_invdeg[node];
    float* out = g_agg2 + node * 288 + lane;
#pragma unroll
    for (int j = 0; j < 9; j++) out[j * 32] = acc[j] * inv;
}

// Fused GEMM + epilogue: x_new = [AGG2 ; x](N x 320) @ B_l(320 x 32) + conv_b, optional relu.
// Thread tile: 4 rows x 4 cols, f32x2 packed FMAs. Block = 128 thr = 64 rows. No smem.
__global__ __launch_bounds__(128) void k_gemm(const float* __restrict__ conv_b,
                                              int inbuf, int l, int do_relu) {
    int lane = threadIdx.x & 31, w = threadIdx.x >> 5;
    int c4 = (lane & 7) * 4;        // output column group
    int rq = lane >> 3;             // row subgroup within warp
    int row = blockIdx.x * 64 + w * 16 + rq * 4;

    const float* __restrict__ xin  = g_xbuf[inbuf];
    float* __restrict__ xout       = g_xbuf[inbuf ^ 1];
    const float* __restrict__ Bl   = g_B + l * (KTOT * HH);
    const float* __restrict__ Abase = g_agg2 + row * 288;

    unsigned long long acc[4][2];
#pragma unroll
    for (int r = 0; r < 4; r++) { acc[r][0] = 0ull; acc[r][1] = 0ull; }

    // K segment 1: AGG2 part (k = 0..287)
#pragma unroll 2
    for (int k = 0; k < 288; k += 4) {
        float4 av[4];
#pragma unroll
        for (int r = 0; r < 4; r++)
            av[r] = __ldg((const float4*)(Abase + r * 288 + k));
#pragma unroll
        for (int kk = 0; kk < 4; kk++) {
            ulonglong2 bb = *(const ulonglong2*)(Bl + (k + kk) * HH + c4);
#pragma unroll
            for (int r = 0; r < 4; r++) {
                float a = (kk == 0) ? av[r].x : (kk == 1) ? av[r].y : (kk == 2) ? av[r].z : av[r].w;
                unsigned long long ar = rep2(a);
                acc[r][0] = fma2(ar, bb.x, acc[r][0]);
                acc[r][1] = fma2(ar, bb.y, acc[r][1]);
            }
        }
    }
    // K segment 2: root path (k = 288..319) reads current x
    const float* __restrict__ Xbase = xin + row * HH;
#pragma unroll
    for (int k = 288; k < KTOT; k += 4) {
        float4 av[4];
#pragma unroll
        for (int r = 0; r < 4; r++)
            av[r] = __ldg((const float4*)(Xbase + r * HH + (k - 288)));
#pragma unroll
        for (int kk = 0; kk < 4; kk++) {
            ulonglong2 bb = *(const ulonglong2*)(Bl + (k + kk) * HH + c4);
#pragma unroll
            for (int r = 0; r < 4; r++) {
                float a = (kk == 0) ? av[r].x : (kk == 1) ? av[r].y : (kk == 2) ? av[r].z : av[r].w;
                unsigned long long ar = rep2(a);
                acc[r][0] = fma2(ar, bb.x, acc[r][0]);
                acc[r][1] = fma2(ar, bb.y, acc[r][1]);
            }
        }
    }

    float cb0 = conv_b[l * HH + c4 + 0];
    float cb1 = conv_b[l * HH + c4 + 1];
    float cb2 = conv_b[l * HH + c4 + 2];
    float cb3 = conv_b[l * HH + c4 + 3];
#pragma unroll
    for (int r = 0; r < 4; r++) {
        float2 lo = unpk(acc[r][0]);
        float2 hi = unpk(acc[r][1]);
        float4 res;
        res.x = lo.x + cb0; res.y = lo.y + cb1; res.z = hi.x + cb2; res.w = hi.y + cb3;
        if (do_relu) {
            res.x = fmaxf(res.x, 0.0f); res.y = fmaxf(res.y, 0.0f);
            res.z = fmaxf(res.z, 0.0f); res.w = fmaxf(res.w, 0.0f);
        }
        *(float4*)(xout + (row + r) * HH + c4) = res;
    }
}

// ---------------- readout ----------------
// warp per (batch, pair). p<64: loop_edge (result - fhM); p>=64: loop_pair (negated).
__global__ __launch_bounds__(256) void k_final(const int* __restrict__ metal_idx,
                                               const int* __restrict__ loop_edge,
                                               const int* __restrict__ loop_pair,
                                               const float* __restrict__ f_w,
                                               const float* __restrict__ f_b,
                                               float* __restrict__ out) {
    int gw = blockIdx.x * 8 + (threadIdx.x >> 5);  // 0..4095
    int lane = threadIdx.x & 31;
    int b = gw >> 7, p = gw & 127;
    const float* __restrict__ x = g_xbuf[0];       // final features land in buf 0

    int mnode = b * NPER + metal_idx[b];
    float xm = x[mnode * HH + lane];

    int s, t;
    if (p < 64) {
        s = loop_edge[(b * 64 + p) * 2 + 0];
        t = loop_edge[(b * 64 + p) * 2 + 1];
    } else {
        int q = p - 64;
        s = loop_pair[(b * 64 + q) * 2 + 0];
        t = loop_pair[(b * 64 + q) * 2 + 1];
    }
    float xs = x[(b * NPER + s) * HH + lane];
    float xt = x[(b * NPER + t) * HH + lane];
    float v  = xm * (xs + xt) - xs * xt;
    float fh = xm * f_w[lane];
#pragma unroll
    for (int off = 16; off; off >>= 1) {
        v  += __shfl_xor_sync(0xFFFFFFFFu, v, off);
        fh += __shfl_xor_sync(0xFFFFFFFFu, fh, off);
    }
    if (lane == 0)
        out[b * 128 + p] = (p < 64) ? (v - (fh + f_b[0])) : -v;
}

// ---------------- launch ----------------
extern "C" void kernel_launch(void* const* d_in, const int* in_sizes, int n_in,
                              void* d_out, int out_size) {
    const int*   x_nodes    = (const int*)d_in[0];
    const int*   edge_index = (const int*)d_in[1];
    const int*   edge_attr  = (const int*)d_in[2];
    const int*   metal_idx  = (const int*)d_in[3];
    const int*   loop_edge  = (const int*)d_in[4];
    const int*   loop_pair  = (const int*)d_in[5];
    const float* node_emb   = (const float*)d_in[6];
    const float* edge_emb   = (const float*)d_in[7];
    const float* lin_w      = (const float*)d_in[8];
    const float* lin_b      = (const float*)d_in[9];
    const float* root_w     = (const float*)d_in[10];
    const float* conv_b     = (const float*)d_in[11];
    const float* f_w        = (const float*)d_in[12];
    const float* f_b        = (const float*)d_in[13];
    float* out = (float*)d_out;

    k_init   <<<(NN * HH) / 256, 256>>>(x_nodes, node_emb);
    k_prepB  <<<(NLAY * KTOT * HH) / 256, 256>>>(lin_w, lin_b, root_w);
    k_count  <<<EE / 256, 256>>>(edge_index);
    k_scan   <<<1, 1024>>>();
    k_scatter<<<EE / 256, 256>>>(edge_index, edge_attr);

    for (int l = 0; l < NLAY; l++) {
        int inb = l & 1;   // l even: x in buf0 -> buf1; l odd: buf1 -> buf0
        k_edge<<<NN / 8, 256>>>(edge_emb, inb, l);
        k_gemm<<<NN / 64, 128>>>(conv_b, inb, l, (l < NLAY - 1) ? 1 : 0);
    }

    k_final<<<(BBAT * 128) / 8, 256>>>(metal_idx, loop_edge, loop_pair, f_w, f_b, out);
}

// round 2
// speedup vs baseline: 1.4745x; 1.4745x over previous
#include <cuda_runtime.h>

// ---------------- problem constants ----------------
#define NN    16384     // nodes (B*NPER)
#define EE    65536     // edges
#define HH    32        // hidden
#define BBAT  32        // batch
#define NPERB 512
#define NLAY  4
#define KTOT  320       // 256 (c⊗x) + 32 (bias path) + 32 (root path)
#define NPB   32        // nodes per layer-block
#define APITCH 292      // smem A row pitch (floats): 292 mod 32 = 4 -> conflict-free GEMM reads

// ---------------- scratch (static device globals; zero-initialized at load) ----
__device__ __align__(16) float g_xbuf[2][NN * HH];     // ping-pong node features
__device__ __align__(16) float g_B[NLAY * KTOT * HH];  // fused per-layer weights (160KB)
__device__ int   g_deg[NN];                            // zeroed by k_final for next replay
__device__ float g_invdeg[NN];
__device__ int   g_rowstart[NN + 1];
__device__ int   g_cursor[NN];
__device__ int   g_payload[EE];                        // (src<<4)|attr, grouped by dst
__device__ int   g_bsum[64];

// ---------------- f32x2 helpers ----------------
__device__ __forceinline__ unsigned long long fma2(unsigned long long a,
                                                   unsigned long long b,
                                                   unsigned long long c) {
    unsigned long long d;
    asm("fma.rn.f32x2 %0, %1, %2, %3;" : "=l"(d) : "l"(a), "l"(b), "l"(c));
    return d;
}
__device__ __forceinline__ unsigned long long rep2(float a) {
    unsigned int u = __float_as_uint(a);
    unsigned long long d;
    asm("mov.b64 %0, {%1, %1};" : "=l"(d) : "r"(u));
    return d;
}
__device__ __forceinline__ float2 unpk(unsigned long long v) {
    unsigned int lo, hi;
    asm("mov.b64 {%0, %1}, %2;" : "=r"(lo), "=r"(hi) : "l"(v));
    return make_float2(__uint_as_float(lo), __uint_as_float(hi));
}

// ================= K1: fused setup (init x, build B, count degrees) ==========
// blocks [0,2048): x init; [2048,2208): B build; [2208,2464): degree count.
// g_deg must be zero at entry: true at load, and k_final re-zeroes it.
__global__ __launch_bounds__(256) void k_setup(const int* __restrict__ xn,
                                               const float* __restrict__ nemb,
                                               const float* __restrict__ lin_w,
                                               const float* __restrict__ lin_b,
                                               const float* __restrict__ root_w,
                                               const int* __restrict__ edge_index) {
    int b = blockIdx.x, t = threadIdx.x;
    if (b < 2048) {
        int i = b * 256 + t;                 // < NN*HH
        g_xbuf[0][i] = nemb[xn[i >> 5] * HH + (i & 31)];
    } else if (b < 2208) {
        int i = (b - 2048) * 256 + t;        // < NLAY*KTOT*HH
        int l = i / (KTOT * HH);
        int rem = i - l * KTOT * HH;
        int r = rem >> 5, o = rem & 31;
        float v;
        if (r < 256)      v = lin_w[l * 8192 + (r >> 5) * 1024 + (r & 31) * 32 + o];
        else if (r < 288) v = lin_b[l * 1024 + (r - 256) * 32 + o];
        else              v = root_w[l * 1024 + (r - 288) * 32 + o];
        g_B[i] = v;
    } else {
        int e = (b - 2208) * 256 + t;        // < EE
        atomicAdd(&g_deg[edge_index[EE + e]], 1);
    }
}

// ================= K2/K3: hierarchical scan ==================================
__global__ __launch_bounds__(256) void k_scan1() {
    __shared__ int sw[8];
    int tid = threadIdx.x, w = tid >> 5, lane = tid & 31;
    int n = blockIdx.x * 256 + tid;
    int d = g_deg[n];
    int s = d;
#pragma unroll
    for (int off = 16; off; off >>= 1) s += __shfl_down_sync(0xFFFFFFFFu, s, off);
    if (lane == 0) sw[w] = s;
    __syncthreads();
    if (tid == 0) {
        int tot = 0;
#pragma unroll
        for (int j = 0; j < 8; j++) tot += sw[j];
        g_bsum[blockIdx.x] = tot;
    }
}

__global__ __launch_bounds__(256) void k_scan2() {
    __shared__ int sb[64];
    __shared__ int sw[8];
    int tid = threadIdx.x, w = tid >> 5, lane = tid & 31;
    int n = blockIdx.x * 256 + tid;
    if (tid < 64) sb[tid] = g_bsum[tid];
    int d = g_deg[n];
    __syncthreads();
    int base = 0;
    for (int j = 0; j < blockIdx.x; j++) base += sb[j];   // broadcast reads
    int incl = d;
#pragma unroll
    for (int off = 1; off < 32; off <<= 1) {
        int v = __shfl_up_sync(0xFFFFFFFFu, incl, off);
        if (lane >= off) incl += v;
    }
    if (lane == 31) sw[w] = incl;
    __syncthreads();
    int woff = 0;
#pragma unroll
    for (int j = 0; j < 8; j++) if (j < w) woff += sw[j];
    int excl = base + woff + incl - d;
    g_rowstart[n] = excl;
    g_cursor[n]   = excl;
    g_invdeg[n]   = 1.0f / (float)(d > 0 ? d : 1);
    if (n == NN - 1) g_rowstart[NN] = excl + d;
}

// ================= K4: scatter edges into CSR ================================
__global__ __launch_bounds__(256) void k_scatter(const int* __restrict__ edge_index,
                                                 const int* __restrict__ edge_attr) {
    int e = blockIdx.x * 256 + threadIdx.x;
    int d = edge_index[EE + e];
    int pos = atomicAdd(&g_cursor[d], 1);
    g_payload[pos] = (edge_index[e] << 4) | edge_attr[e];
}

// ================= fused layer: edge aggregation (smem) + GEMM ===============
// Block: 256 threads, 32 nodes. Phase 1: 8 warps x 4 interleaved nodes, lane=feature.
// Phase 2: 128 threads, thread tile = 4 rows x 2 cols (f32x2), A from smem, B via L1.
__global__ __launch_bounds__(256) void k_layer(const float* __restrict__ eemb,
                                               const float* __restrict__ conv_b,
                                               int inbuf, int l, int do_relu) {
    __shared__ float As[NPB][APITCH];
    __shared__ float cs[128];
    int tid = threadIdx.x;
    if (tid < 128) cs[tid] = fmaxf(eemb[l * 128 + tid], 0.0f);

    const float* __restrict__ xin = g_xbuf[inbuf];
    int w = tid >> 5, lane = tid & 31;
    int nl0 = w * 4;                       // local node base for this warp
    int ng0 = blockIdx.x * NPB + nl0;      // global node base

    // rowstart[ng0 .. ng0+4] via lanes 0..4 + shuffle
    int rs = 0;
    if (lane < 5) rs = g_rowstart[ng0 + lane];
    int r0 = __shfl_sync(0xFFFFFFFFu, rs, 0);
    int r1 = __shfl_sync(0xFFFFFFFFu, rs, 1);
    int r2 = __shfl_sync(0xFFFFFFFFu, rs, 2);
    int r3 = __shfl_sync(0xFFFFFFFFu, rs, 3);
    int r4 = __shfl_sync(0xFFFFFFFFu, rs, 4);
    int beg[4] = {r0, r1, r2, r3};
    int cnt[4] = {r1 - r0, r2 - r1, r3 - r2, r4 - r3};
    int maxc = max(max(cnt[0], cnt[1]), max(cnt[2], cnt[3]));

    __syncthreads();   // cs ready

    float acc[4][9];
#pragma unroll
    for (int i = 0; i < 4; i++)
#pragma unroll
        for (int j = 0; j < 9; j++) acc[i][j] = 0.0f;

    for (int t = 0; t < maxc; t++) {
        int   p[4];
        float xv[4];
#pragma unroll
        for (int i = 0; i < 4; i++) p[i] = (t < cnt[i]) ? g_payload[beg[i] + t] : -1;
#pragma unroll
        for (int i = 0; i < 4; i++)
            xv[i] = (p[i] >= 0) ? __ldg(&xin[(p[i] >> 4) * HH + lane]) : 0.0f;
#pragma unroll
        for (int i = 0; i < 4; i++) {
            const float* cc = &cs[(p[i] & 15) * 8];
#pragma unroll
            for (int j = 0; j < 8; j++) acc[i][j] = fmaf(cc[j], xv[i], acc[i][j]);
            acc[i][8] += xv[i];
        }
    }

#pragma unroll
    for (int i = 0; i < 4; i++) {
        float inv = g_invdeg[ng0 + i];
#pragma unroll
        for (int j = 0; j < 9; j++) As[nl0 + i][j * 32 + lane] = acc[i][j] * inv;
    }
    __syncthreads();

    // ---------------- GEMM phase: 128 threads ----------------
    if (tid < 128) {
        int rg = tid & 7;          // row within group of 8
        int cg = tid >> 3;         // 0..15 -> column pair
        int c2 = cg * 2;
        const float* __restrict__ Bl = g_B + l * (KTOT * HH);

        unsigned long long a0 = 0ull, a1 = 0ull, a2 = 0ull, a3 = 0ull;

#pragma unroll 4
        for (int k = 0; k < 288; k += 4) {
            float4 av0 = *(const float4*)&As[rg     ][k];
            float4 av1 = *(const float4*)&As[rg +  8][k];
            float4 av2 = *(const float4*)&As[rg + 16][k];
            float4 av3 = *(const float4*)&As[rg + 24][k];
#pragma unroll
            for (int kk = 0; kk < 4; kk++) {
                unsigned long long bb = *(const unsigned long long*)(Bl + (k + kk) * HH + c2);
                float f0 = (kk == 0) ? av0.x : (kk == 1) ? av0.y : (kk == 2) ? av0.z : av0.w;
                float f1 = (kk == 0) ? av1.x : (kk == 1) ? av1.y : (kk == 2) ? av1.z : av1.w;
                float f2 = (kk == 0) ? av2.x : (kk == 1) ? av2.y : (kk == 2) ? av2.z : av2.w;
                float f3 = (kk == 0) ? av3.x : (kk == 1) ? av3.y : (kk == 2) ? av3.z : av3.w;
                a0 = fma2(rep2(f0), bb, a0);
                a1 = fma2(rep2(f1), bb, a1);
                a2 = fma2(rep2(f2), bb, a2);
                a3 = fma2(rep2(f3), bb, a3);
            }
        }
        // root segment: k = 288..319 uses current x (own rows, from global)
        const float* __restrict__ Xb = xin + (blockIdx.x * NPB) * HH;
#pragma unroll
        for (int k = 0; k < 32; k += 4) {
            float4 av0 = __ldg((const float4*)(Xb + (rg     ) * HH + k));
            float4 av1 = __ldg((const float4*)(Xb + (rg +  8) * HH + k));
            float4 av2 = __ldg((const float4*)(Xb + (rg + 16) * HH + k));
            float4 av3 = __ldg((const float4*)(Xb + (rg + 24) * HH + k));
#pragma unroll
            for (int kk = 0; kk < 4; kk++) {
                unsigned long long bb = *(const unsigned long long*)(Bl + (288 + k + kk) * HH + c2);
                float f0 = (kk == 0) ? av0.x : (kk == 1) ? av0.y : (kk == 2) ? av0.z : av0.w;
                float f1 = (kk == 0) ? av1.x : (kk == 1) ? av1.y : (kk == 2) ? av1.z : av1.w;
                float f2 = (kk == 0) ? av2.x : (kk == 1) ? av2.y : (kk == 2) ? av2.z : av2.w;
                float f3 = (kk == 0) ? av3.x : (kk == 1) ? av3.y : (kk == 2) ? av3.z : av3.w;
                a0 = fma2(rep2(f0), bb, a0);
                a1 = fma2(rep2(f1), bb, a1);
                a2 = fma2(rep2(f2), bb, a2);
                a3 = fma2(rep2(f3), bb, a3);
            }
        }

        float cbx = conv_b[l * HH + c2];
        float cby = conv_b[l * HH + c2 + 1];
        float* __restrict__ xout = g_xbuf[inbuf ^ 1];
        unsigned long long accs[4] = {a0, a1, a2, a3};
#pragma unroll
        for (int r = 0; r < 4; r++) {
            int row = blockIdx.x * NPB + rg + r * 8;
            float2 v = unpk(accs[r]);
            v.x += cbx; v.y += cby;
            if (do_relu) { v.x = fmaxf(v.x, 0.0f); v.y = fmaxf(v.y, 0.0f); }
            *(float2*)&xout[row * HH + c2] = v;
        }
    }
}

// ================= readout (+ zero g_deg for next replay) ====================
__global__ __launch_bounds__(256) void k_final(const int* __restrict__ metal_idx,
                                               const int* __restrict__ loop_edge,
                                               const int* __restrict__ loop_pair,
                                               const float* __restrict__ f_w,
                                               const float* __restrict__ f_b,
                                               float* __restrict__ out) {
    int gid = blockIdx.x * 256 + threadIdx.x;
    if (gid < NN) g_deg[gid] = 0;          // prepare next launch's k_setup count

    int gw = blockIdx.x * 8 + (threadIdx.x >> 5);  // 0..4095
    int lane = threadIdx.x & 31;
    int b = gw >> 7, p = gw & 127;
    const float* __restrict__ x = g_xbuf[0];       // final features land in buf 0

    int mnode = b * NPERB + metal_idx[b];
    float xm = x[mnode * HH + lane];

    int s, t;
    if (p < 64) {
        s = loop_edge[(b * 64 + p) * 2 + 0];
        t = loop_edge[(b * 64 + p) * 2 + 1];
    } else {
        int q = p - 64;
        s = loop_pair[(b * 64 + q) * 2 + 0];
        t = loop_pair[(b * 64 + q) * 2 + 1];
    }
    float xs = x[(b * NPERB + s) * HH + lane];
    float xt = x[(b * NPERB + t) * HH + lane];
    float v  = xm * (xs + xt) - xs * xt;
    float fh = xm * f_w[lane];
#pragma unroll
    for (int off = 16; off; off >>= 1) {
        v  += __shfl_xor_sync(0xFFFFFFFFu, v, off);
        fh += __shfl_xor_sync(0xFFFFFFFFu, fh, off);
    }
    if (lane == 0)
        out[b * 128 + p] = (p < 64) ? (v - (fh + f_b[0])) : -v;
}

// ================= launch ====================================================
extern "C" void kernel_launch(void* const* d_in, const int* in_sizes, int n_in,
                              void* d_out, int out_size) {
    const int*   x_nodes    = (const int*)d_in[0];
    const int*   edge_index = (const int*)d_in[1];
    const int*   edge_attr  = (const int*)d_in[2];
    const int*   metal_idx  = (const int*)d_in[3];
    const int*   loop_edge  = (const int*)d_in[4];
    const int*   loop_pair  = (const int*)d_in[5];
    const float* node_emb   = (const float*)d_in[6];
    const float* edge_emb   = (const float*)d_in[7];
    const float* lin_w      = (const float*)d_in[8];
    const float* lin_b      = (const float*)d_in[9];
    const float* root_w     = (const float*)d_in[10];
    const float* conv_b     = (const float*)d_in[11];
    const float* f_w        = (const float*)d_in[12];
    const float* f_b        = (const float*)d_in[13];
    float* out = (float*)d_out;

    k_setup  <<<2464, 256>>>(x_nodes, node_emb, lin_w, lin_b, root_w, edge_index);
    k_scan1  <<<64, 256>>>();
    k_scan2  <<<64, 256>>>();
    k_scatter<<<256, 256>>>(edge_index, edge_attr);

    for (int l = 0; l < NLAY; l++) {
        int inb = l & 1;
        k_layer<<<NN / NPB, 256>>>(edge_emb, conv_b, inb, l, (l < NLAY - 1) ? 1 : 0);
    }

    k_final<<<512, 256>>>(metal_idx, loop_edge, loop_pair, f_w, f_b, out);
}

// round 3
// speedup vs baseline: 1.7283x; 1.1721x over previous
#include <cuda_runtime.h>

// ---------------- problem constants ----------------
#define NN    16384     // nodes (B*NPER)
#define EE    65536     // edges
#define HH    32        // hidden
#define BBAT  32        // batch
#define NPERB 512
#define NLAY  4
#define KTOT  320       // 256 (c (x) x) + 32 (bias path) + 32 (root path)
#define NPB   32        // nodes per layer-block
#define APITCH 321      // A pitch (floats), 321 mod 32 == 1 -> conflict-free lane=row LDS.32
#define RPITCH 36       // reduction staging pitch
// dynamic smem float offsets
#define OFF_AS 0
#define OFF_BS 10272    // 32*321
#define OFF_CS 20512    // +320*32
#define SMEMF  20640
#define SMEMB  (SMEMF * 4)

// ---------------- scratch (static device globals) ----------------
__device__ __align__(16) float g_xbuf[2][NN * HH];     // ping-pong node features
__device__ __align__(16) float g_B[NLAY * KTOT * HH];  // fused per-layer weights (160KB)
__device__ int   g_deg[NN];                            // zeroed by k_final for next replay
__device__ float g_invdeg[NN];
__device__ int   g_rowstart[NN + 1];
__device__ int   g_cursor[NN];
__device__ int   g_payload[EE];                        // (src<<4)|attr, grouped by dst
__device__ int   g_bsum[64];

// ---------------- f32x2 helpers ----------------
__device__ __forceinline__ unsigned long long fma2(unsigned long long a,
                                                   unsigned long long b,
                                                   unsigned long long c) {
    unsigned long long d;
    asm("fma.rn.f32x2 %0, %1, %2, %3;" : "=l"(d) : "l"(a), "l"(b), "l"(c));
    return d;
}
__device__ __forceinline__ unsigned long long rep2(float a) {
    unsigned int u = __float_as_uint(a);
    unsigned long long d;
    asm("mov.b64 %0, {%1, %1};" : "=l"(d) : "r"(u));
    return d;
}

// ================= K1: fused setup (init x, build B, count degrees) ==========
__global__ __launch_bounds__(256) void k_setup(const int* __restrict__ xn,
                                               const float* __restrict__ nemb,
                                               const float* __restrict__ lin_w,
                                               const float* __restrict__ lin_b,
                                               const float* __restrict__ root_w,
                                               const int* __restrict__ edge_index) {
    int b = blockIdx.x, t = threadIdx.x;
    if (b < 2048) {
        int i = b * 256 + t;                 // < NN*HH
        g_xbuf[0][i] = nemb[xn[i >> 5] * HH + (i & 31)];
    } else if (b < 2208) {
        int i = (b - 2048) * 256 + t;        // < NLAY*KTOT*HH
        int l = i / (KTOT * HH);
        int rem = i - l * KTOT * HH;
        int r = rem >> 5, o = rem & 31;
        float v;
        if (r < 256)      v = lin_w[l * 8192 + (r >> 5) * 1024 + (r & 31) * 32 + o];
        else if (r < 288) v = lin_b[l * 1024 + (r - 256) * 32 + o];
        else              v = root_w[l * 1024 + (r - 288) * 32 + o];
        g_B[i] = v;
    } else {
        int e = (b - 2208) * 256 + t;        // < EE
        atomicAdd(&g_deg[edge_index[EE + e]], 1);
    }
}

// ================= K2/K3: hierarchical scan ==================================
__global__ __launch_bounds__(256) void k_scan1() {
    __shared__ int sw[8];
    int tid = threadIdx.x, w = tid >> 5, lane = tid & 31;
    int n = blockIdx.x * 256 + tid;
    int d = g_deg[n];
    int s = d;
#pragma unroll
    for (int off = 16; off; off >>= 1) s += __shfl_down_sync(0xFFFFFFFFu, s, off);
    if (lane == 0) sw[w] = s;
    __syncthreads();
    if (tid == 0) {
        int tot = 0;
#pragma unroll
        for (int j = 0; j < 8; j++) tot += sw[j];
        g_bsum[blockIdx.x] = tot;
    }
}

__global__ __launch_bounds__(256) void k_scan2() {
    __shared__ int sb[64];
    __shared__ int sw[8];
    int tid = threadIdx.x, w = tid >> 5, lane = tid & 31;
    int n = blockIdx.x * 256 + tid;
    if (tid < 64) sb[tid] = g_bsum[tid];
    int d = g_deg[n];
    __syncthreads();
    int base = 0;
    for (int j = 0; j < blockIdx.x; j++) base += sb[j];
    int incl = d;
#pragma unroll
    for (int off = 1; off < 32; off <<= 1) {
        int v = __shfl_up_sync(0xFFFFFFFFu, incl, off);
        if (lane >= off) incl += v;
    }
    if (lane == 31) sw[w] = incl;
    __syncthreads();
    int woff = 0;
#pragma unroll
    for (int j = 0; j < 8; j++) if (j < w) woff += sw[j];
    int excl = base + woff + incl - d;
    g_rowstart[n] = excl;
    g_cursor[n]   = excl;
    g_invdeg[n]   = 1.0f / (float)(d > 0 ? d : 1);
    if (n == NN - 1) g_rowstart[NN] = excl + d;
}

// ================= K4: scatter edges into CSR ================================
__global__ __launch_bounds__(256) void k_scatter(const int* __restrict__ edge_index,
                                                 const int* __restrict__ edge_attr) {
    int e = blockIdx.x * 256 + threadIdx.x;
    int d = edge_index[EE + e];
    int pos = atomicAdd(&g_cursor[d], 1);
    g_payload[pos] = (edge_index[e] << 4) | edge_attr[e];
}

// ================= fused layer =================================================
// Phase 1 (edge agg): 8 warps x 4 interleaved nodes, lane = feature. Writes A
//   (32 x 320, pitch 321) into smem: cols 0..255 c(x)x, 256..287 bias path
//   (both scaled by 1/deg), 288..319 = own x (root path).
// Phase 2 (GEMM): lane = row, warp w takes k-slice [w*40, w*40+40). Per k:
//   1 conflict-free LDS.32 (A) + 8 broadcast LDS.128 (B row) + 16 FFMA2 into
//   16 f32x2 accumulators (full 32-col output). Partials staged in smem
//   (reusing the A region) and reduced by all 256 threads.
__global__ __launch_bounds__(256) void k_layer(const float* __restrict__ eemb,
                                               const float* __restrict__ conv_b,
                                               int inbuf, int l, int do_relu) {
    extern __shared__ float smem[];
    float* As = smem + OFF_AS;
    float* Bs = smem + OFF_BS;
    float* cs = smem + OFF_CS;
    int tid = threadIdx.x;

    // stage B_l (40KB) into smem; issued first so latency hides under edge phase
    const float4* gBl = (const float4*)(g_B + l * (KTOT * HH));
#pragma unroll
    for (int i = 0; i < 10; i++)
        ((float4*)Bs)[tid + i * 256] = __ldg(gBl + tid + i * 256);
    if (tid < 128) cs[tid] = fmaxf(eemb[l * 128 + tid], 0.0f);

    const float* __restrict__ xin = g_xbuf[inbuf];
    int w = tid >> 5, lane = tid & 31;
    int nl0 = w * 4;
    int ng0 = blockIdx.x * NPB + nl0;

    int rs = 0;
    if (lane < 5) rs = g_rowstart[ng0 + lane];
    int r0 = __shfl_sync(0xFFFFFFFFu, rs, 0);
    int r1 = __shfl_sync(0xFFFFFFFFu, rs, 1);
    int r2 = __shfl_sync(0xFFFFFFFFu, rs, 2);
    int r3 = __shfl_sync(0xFFFFFFFFu, rs, 3);
    int r4 = __shfl_sync(0xFFFFFFFFu, rs, 4);
    int beg[4] = {r0, r1, r2, r3};
    int cnt[4] = {r1 - r0, r2 - r1, r3 - r2, r4 - r3};
    int maxc = max(max(cnt[0], cnt[1]), max(cnt[2], cnt[3]));

    float acc[4][9];
#pragma unroll
    for (int i = 0; i < 4; i++)
#pragma unroll
        for (int j = 0; j < 9; j++) acc[i][j] = 0.0f;

    __syncthreads();   // cs (and nothing else yet) needed below

    for (int t = 0; t < maxc; t++) {
        int   p[4];
        float xv[4];
#pragma unroll
        for (int i = 0; i < 4; i++) p[i] = (t < cnt[i]) ? g_payload[beg[i] + t] : -1;
#pragma unroll
        for (int i = 0; i < 4; i++)
            xv[i] = (p[i] >= 0) ? __ldg(&xin[(p[i] >> 4) * HH + lane]) : 0.0f;
#pragma unroll
        for (int i = 0; i < 4; i++) {
            const float* cc = &cs[(p[i] & 15) * 8];
#pragma unroll
            for (int j = 0; j < 8; j++) acc[i][j] = fmaf(cc[j], xv[i], acc[i][j]);
            acc[i][8] += xv[i];
        }
    }

#pragma unroll
    for (int i = 0; i < 4; i++) {
        float inv = g_invdeg[ng0 + i];
        float* Arow = As + (nl0 + i) * APITCH;
#pragma unroll
        for (int j = 0; j < 9; j++) Arow[j * 32 + lane] = acc[i][j] * inv;
        Arow[288 + lane] = xin[(ng0 + i) * HH + lane];   // root path, unscaled
    }
    __syncthreads();

    // ---------------- GEMM phase: lane = row, warp = k-slice ----------------
    {
        const float* __restrict__ Ar = As + lane * APITCH;
        unsigned long long ac[16];
#pragma unroll
        for (int c = 0; c < 16; c++) ac[c] = 0ull;

        int k0 = w * 40;
#pragma unroll 2
        for (int k = k0; k < k0 + 40; k++) {
            unsigned long long ar = rep2(Ar[k]);
            const ulonglong2* Br = (const ulonglong2*)(Bs + (k << 5));
#pragma unroll
            for (int q = 0; q < 8; q++) {
                ulonglong2 b = Br[q];
                ac[2 * q]     = fma2(ar, b.x, ac[2 * q]);
                ac[2 * q + 1] = fma2(ar, b.y, ac[2 * q + 1]);
            }
        }
        __syncthreads();   // everyone done READING As; safe to overwrite
        // stage partials: warp w block at word offset w*1152, row pitch RPITCH
        float* Rp = As + w * 1152 + lane * RPITCH;
#pragma unroll
        for (int c = 0; c < 16; c++)
            *(unsigned long long*)(Rp + 2 * c) = ac[c];
    }
    __syncthreads();

    // ---------------- reduce 8 partials + epilogue ----------------
    {
        int row = tid >> 3, c4 = (tid & 7) * 4;
        float4 s = make_float4(0.f, 0.f, 0.f, 0.f);
#pragma unroll
        for (int w2 = 0; w2 < 8; w2++) {
            float4 v = *(const float4*)(As + w2 * 1152 + row * RPITCH + c4);
            s.x += v.x; s.y += v.y; s.z += v.z; s.w += v.w;
        }
        s.x += conv_b[l * HH + c4 + 0];
        s.y += conv_b[l * HH + c4 + 1];
        s.z += conv_b[l * HH + c4 + 2];
        s.w += conv_b[l * HH + c4 + 3];
        if (do_relu) {
            s.x = fmaxf(s.x, 0.f); s.y = fmaxf(s.y, 0.f);
            s.z = fmaxf(s.z, 0.f); s.w = fmaxf(s.w, 0.f);
        }
        float* __restrict__ xout = g_xbuf[inbuf ^ 1];
        *(float4*)&xout[(blockIdx.x * NPB + row) * HH + c4] = s;
    }
}

// ================= readout (+ zero g_deg for next replay) ====================
__global__ __launch_bounds__(256) void k_final(const int* __restrict__ metal_idx,
                                               const int* __restrict__ loop_edge,
                                               const int* __restrict__ loop_pair,
                                               const float* __restrict__ f_w,
                                               const float* __restrict__ f_b,
                                               float* __restrict__ out) {
    int gid = blockIdx.x * 256 + threadIdx.x;
    if (gid < NN) g_deg[gid] = 0;

    int gw = blockIdx.x * 8 + (threadIdx.x >> 5);
    int lane = threadIdx.x & 31;
    int b = gw >> 7, p = gw & 127;
    const float* __restrict__ x = g_xbuf[0];   // NLAY even -> final in buf 0

    int mnode = b * NPERB + metal_idx[b];
    float xm = x[mnode * HH + lane];

    int s, t;
    if (p < 64) {
        s = loop_edge[(b * 64 + p) * 2 + 0];
        t = loop_edge[(b * 64 + p) * 2 + 1];
    } else {
        int q = p - 64;
        s = loop_pair[(b * 64 + q) * 2 + 0];
        t = loop_pair[(b * 64 + q) * 2 + 1];
    }
    float xs = x[(b * NPERB + s) * HH + lane];
    float xt = x[(b * NPERB + t) * HH + lane];
    float v  = xm * (xs + xt) - xs * xt;
    float fh = xm * f_w[lane];
#pragma unroll
    for (int off = 16; off; off >>= 1) {
        v  += __shfl_xor_sync(0xFFFFFFFFu, v, off);
        fh += __shfl_xor_sync(0xFFFFFFFFu, fh, off);
    }
    if (lane == 0)
        out[b * 128 + p] = (p < 64) ? (v - (fh + f_b[0])) : -v;
}

// ================= launch ====================================================
extern "C" void kernel_launch(void* const* d_in, const int* in_sizes, int n_in,
                              void* d_out, int out_size) {
    const int*   x_nodes    = (const int*)d_in[0];
    const int*   edge_index = (const int*)d_in[1];
    const int*   edge_attr  = (const int*)d_in[2];
    const int*   metal_idx  = (const int*)d_in[3];
    const int*   loop_edge  = (const int*)d_in[4];
    const int*   loop_pair  = (const int*)d_in[5];
    const float* node_emb   = (const float*)d_in[6];
    const float* edge_emb   = (const float*)d_in[7];
    const float* lin_w      = (const float*)d_in[8];
    const float* lin_b      = (const float*)d_in[9];
    const float* root_w     = (const float*)d_in[10];
    const float* conv_b     = (const float*)d_in[11];
    const float* f_w        = (const float*)d_in[12];
    const float* f_b        = (const float*)d_in[13];
    float* out = (float*)d_out;

    cudaFuncSetAttribute(k_layer, cudaFuncAttributeMaxDynamicSharedMemorySize, SMEMB);

    k_setup  <<<2464, 256>>>(x_nodes, node_emb, lin_w, lin_b, root_w, edge_index);
    k_scan1  <<<64, 256>>>();
    k_scan2  <<<64, 256>>>();
    k_scatter<<<256, 256>>>(edge_index, edge_attr);

    for (int l = 0; l < NLAY; l++) {
        int inb = l & 1;
        k_layer<<<NN / NPB, 256, SMEMB>>>(edge_emb, conv_b, inb, l, (l < NLAY - 1) ? 1 : 0);
    }

    k_final<<<512, 256>>>(metal_idx, loop_edge, loop_pair, f_w, f_b, out);
}

// round 4
// speedup vs baseline: 1.9945x; 1.1540x over previous
#include <cuda_runtime.h>

// ---------------- problem constants ----------------
#define NN    16384     // nodes (B*NPER)
#define EE    65536     // edges
#define HH    32        // hidden
#define BBAT  32        // batch
#define NPERB 512
#define NLAY  4
#define KTOT  320       // 256 (c (x) x) + 32 (bias path) + 32 (root path)
#define NPB   32        // nodes per layer-block
#define APITCH 321      // A pitch (floats), 321 mod 32 == 1 -> conflict-free lane=row LDS.32
#define RPITCH 36       // reduction staging pitch
// dynamic smem float offsets
#define OFF_AS 0
#define OFF_BS 10272    // 32*321
#define OFF_CS 20512    // +320*32
#define SMEMF  20640
#define SMEMB  (SMEMF * 4)

// ---------------- scratch (static device globals) ----------------
__device__ __align__(16) float g_xbuf[2][NN * HH];     // ping-pong node features
__device__ __align__(16) float g_B[NLAY * KTOT * HH];  // fused per-layer weights (160KB)
__device__ int   g_deg[NN];                            // zeroed by k_final for next replay
__device__ float g_invdeg[NN];
__device__ int   g_rowstart[NN + 1];
__device__ int   g_cursor[NN];
__device__ int   g_payload[EE];                        // (src<<4)|attr, grouped by dst
__device__ int   g_bsum[64];

// ---------------- f32x2 helpers ----------------
__device__ __forceinline__ unsigned long long fma2(unsigned long long a,
                                                   unsigned long long b,
                                                   unsigned long long c) {
    unsigned long long d;
    asm("fma.rn.f32x2 %0, %1, %2, %3;" : "=l"(d) : "l"(a), "l"(b), "l"(c));
    return d;
}
__device__ __forceinline__ unsigned long long rep2(float a) {
    unsigned int u = __float_as_uint(a);
    unsigned long long d;
    asm("mov.b64 %0, {%1, %1};" : "=l"(d) : "r"(u));
    return d;
}

// ================= K1: fused setup (init x, build B, count degrees) ==========
// blocks [0,512): x init (float4); [512,672): B build; [672,736): degree count (int4).
__global__ __launch_bounds__(256) void k_setup(const int* __restrict__ xn,
                                               const float* __restrict__ nemb,
                                               const float* __restrict__ lin_w,
                                               const float* __restrict__ lin_b,
                                               const float* __restrict__ root_w,
                                               const int* __restrict__ edge_index) {
    int b = blockIdx.x, t = threadIdx.x;
    if (b < 512) {
        int i = b * 256 + t;                 // < NN*HH/4
        int node = i >> 3, q = i & 7;
        float4 v = __ldg((const float4*)(nemb + xn[node] * HH + q * 4));
        ((float4*)g_xbuf[0])[i] = v;
    } else if (b < 672) {
        int i = (b - 512) * 256 + t;         // < NLAY*KTOT*HH
        int l = i / (KTOT * HH);
        int rem = i - l * KTOT * HH;
        int r = rem >> 5, o = rem & 31;
        float v;
        if (r < 256)      v = lin_w[l * 8192 + (r >> 5) * 1024 + (r & 31) * 32 + o];
        else if (r < 288) v = lin_b[l * 1024 + (r - 256) * 32 + o];
        else              v = root_w[l * 1024 + (r - 288) * 32 + o];
        g_B[i] = v;
    } else {
        int i = (b - 672) * 256 + t;         // < EE/4
        int4 d4 = __ldg((const int4*)(edge_index + EE) + i);
        atomicAdd(&g_deg[d4.x], 1);
        atomicAdd(&g_deg[d4.y], 1);
        atomicAdd(&g_deg[d4.z], 1);
        atomicAdd(&g_deg[d4.w], 1);
    }
}

// ================= K2/K3: hierarchical scan ==================================
__global__ __launch_bounds__(256) void k_scan1() {
    __shared__ int sw[8];
    int tid = threadIdx.x, w = tid >> 5, lane = tid & 31;
    int n = blockIdx.x * 256 + tid;
    int d = g_deg[n];
    int s = d;
#pragma unroll
    for (int off = 16; off; off >>= 1) s += __shfl_down_sync(0xFFFFFFFFu, s, off);
    if (lane == 0) sw[w] = s;
    __syncthreads();
    if (tid == 0) {
        int tot = 0;
#pragma unroll
        for (int j = 0; j < 8; j++) tot += sw[j];
        g_bsum[blockIdx.x] = tot;
    }
}

__global__ __launch_bounds__(256) void k_scan2() {
    __shared__ int sb[64];
    __shared__ int sw[8];
    int tid = threadIdx.x, w = tid >> 5, lane = tid & 31;
    int n = blockIdx.x * 256 + tid;
    if (tid < 64) sb[tid] = g_bsum[tid];
    int d = g_deg[n];
    __syncthreads();
    int base = 0;
    for (int j = 0; j < blockIdx.x; j++) base += sb[j];
    int incl = d;
#pragma unroll
    for (int off = 1; off < 32; off <<= 1) {
        int v = __shfl_up_sync(0xFFFFFFFFu, incl, off);
        if (lane >= off) incl += v;
    }
    if (lane == 31) sw[w] = incl;
    __syncthreads();
    int woff = 0;
#pragma unroll
    for (int j = 0; j < 8; j++) if (j < w) woff += sw[j];
    int excl = base + woff + incl - d;
    g_rowstart[n] = excl;
    g_cursor[n]   = excl;
    g_invdeg[n]   = 1.0f / (float)(d > 0 ? d : 1);
    if (n == NN - 1) g_rowstart[NN] = excl + d;
}

// ================= K4: scatter edges into CSR ================================
__global__ __launch_bounds__(256) void k_scatter(const int* __restrict__ edge_index,
                                                 const int* __restrict__ edge_attr) {
    int e = blockIdx.x * 256 + threadIdx.x;
    int d = edge_index[EE + e];
    int pos = atomicAdd(&g_cursor[d], 1);
    g_payload[pos] = (edge_index[e] << 4) | edge_attr[e];
}

// ================= fused layer =================================================
// Phase 1 (edge agg): 8 warps x 4 interleaved nodes, lane = feature. Writes A
//   (32 x 320, pitch 321) into smem.
// Phase 2 (GEMM): lane = row, warp w takes k-slice [w*40, w*40+40). Per k:
//   1 conflict-free LDS.32 (A) + 8 broadcast LDS.128 (B row) + 16 FFMA2.
// __launch_bounds__(256,2): cap regs at 128 so 2 blocks/SM are resident.
__global__ __launch_bounds__(256, 2) void k_layer(const float* __restrict__ eemb,
                                                  const float* __restrict__ conv_b,
                                                  int inbuf, int l, int do_relu) {
    extern __shared__ float smem[];
    float* As = smem + OFF_AS;
    float* Bs = smem + OFF_BS;
    float* cs = smem + OFF_CS;
    int tid = threadIdx.x;

    // stage B_l (40KB) into smem; issued first so latency hides under edge phase
    const float4* gBl = (const float4*)(g_B + l * (KTOT * HH));
#pragma unroll
    for (int i = 0; i < 10; i++)
        ((float4*)Bs)[tid + i * 256] = __ldg(gBl + tid + i * 256);
    if (tid < 128) cs[tid] = fmaxf(eemb[l * 128 + tid], 0.0f);

    const float* __restrict__ xin = g_xbuf[inbuf];
    int w = tid >> 5, lane = tid & 31;
    int nl0 = w * 4;
    int ng0 = blockIdx.x * NPB + nl0;

    int rs = 0;
    if (lane < 5) rs = g_rowstart[ng0 + lane];
    int r0 = __shfl_sync(0xFFFFFFFFu, rs, 0);
    int r1 = __shfl_sync(0xFFFFFFFFu, rs, 1);
    int r2 = __shfl_sync(0xFFFFFFFFu, rs, 2);
    int r3 = __shfl_sync(0xFFFFFFFFu, rs, 3);
    int r4 = __shfl_sync(0xFFFFFFFFu, rs, 4);
    int beg[4] = {r0, r1, r2, r3};
    int cnt[4] = {r1 - r0, r2 - r1, r3 - r2, r4 - r3};
    int maxc = max(max(cnt[0], cnt[1]), max(cnt[2], cnt[3]));

    float acc[4][9];
#pragma unroll
    for (int i = 0; i < 4; i++)
#pragma unroll
        for (int j = 0; j < 9; j++) acc[i][j] = 0.0f;

    __syncthreads();   // cs ready

    for (int t = 0; t < maxc; t++) {
        int   p[4];
        float xv[4];
#pragma unroll
        for (int i = 0; i < 4; i++) p[i] = (t < cnt[i]) ? g_payload[beg[i] + t] : -1;
#pragma unroll
        for (int i = 0; i < 4; i++)
            xv[i] = (p[i] >= 0) ? __ldg(&xin[(p[i] >> 4) * HH + lane]) : 0.0f;
#pragma unroll
        for (int i = 0; i < 4; i++) {
            const float* cc = &cs[(p[i] & 15) * 8];
#pragma unroll
            for (int j = 0; j < 8; j++) acc[i][j] = fmaf(cc[j], xv[i], acc[i][j]);
            acc[i][8] += xv[i];
        }
    }

#pragma unroll
    for (int i = 0; i < 4; i++) {
        float inv = g_invdeg[ng0 + i];
        float* Arow = As + (nl0 + i) * APITCH;
#pragma unroll
        for (int j = 0; j < 9; j++) Arow[j * 32 + lane] = acc[i][j] * inv;
        Arow[288 + lane] = xin[(ng0 + i) * HH + lane];   // root path, unscaled
    }
    __syncthreads();

    // ---------------- GEMM phase: lane = row, warp = k-slice ----------------
    {
        const float* __restrict__ Ar = As + lane * APITCH;
        unsigned long long ac[16];
#pragma unroll
        for (int c = 0; c < 16; c++) ac[c] = 0ull;

        int k0 = w * 40;
#pragma unroll 1
        for (int k = k0; k < k0 + 40; k++) {
            unsigned long long ar = rep2(Ar[k]);
            const ulonglong2* Br = (const ulonglong2*)(Bs + (k << 5));
#pragma unroll
            for (int q = 0; q < 8; q++) {
                ulonglong2 b = Br[q];
                ac[2 * q]     = fma2(ar, b.x, ac[2 * q]);
                ac[2 * q + 1] = fma2(ar, b.y, ac[2 * q + 1]);
            }
        }
        __syncthreads();   // all done READING As; safe to overwrite
        float* Rp = As + w * 1152 + lane * RPITCH;
#pragma unroll
        for (int c = 0; c < 16; c++)
            *(unsigned long long*)(Rp + 2 * c) = ac[c];
    }
    __syncthreads();

    // ---------------- reduce 8 partials + epilogue ----------------
    {
        int row = tid >> 3, c4 = (tid & 7) * 4;
        float4 s = make_float4(0.f, 0.f, 0.f, 0.f);
#pragma unroll
        for (int w2 = 0; w2 < 8; w2++) {
            float4 v = *(const float4*)(As + w2 * 1152 + row * RPITCH + c4);
            s.x += v.x; s.y += v.y; s.z += v.z; s.w += v.w;
        }
        s.x += conv_b[l * HH + c4 + 0];
        s.y += conv_b[l * HH + c4 + 1];
        s.z += conv_b[l * HH + c4 + 2];
        s.w += conv_b[l * HH + c4 + 3];
        if (do_relu) {
            s.x = fmaxf(s.x, 0.f); s.y = fmaxf(s.y, 0.f);
            s.z = fmaxf(s.z, 0.f); s.w = fmaxf(s.w, 0.f);
        }
        float* __restrict__ xout = g_xbuf[inbuf ^ 1];
        *(float4*)&xout[(blockIdx.x * NPB + row) * HH + c4] = s;
    }
}

// ================= readout (+ zero g_deg for next replay) ====================
__global__ __launch_bounds__(256) void k_final(const int* __restrict__ metal_idx,
                                               const int* __restrict__ loop_edge,
                                               const int* __restrict__ loop_pair,
                                               const float* __restrict__ f_w,
                                               const float* __restrict__ f_b,
                                               float* __restrict__ out) {
    int gid = blockIdx.x * 256 + threadIdx.x;
    if (gid < NN) g_deg[gid] = 0;

    int gw = blockIdx.x * 8 + (threadIdx.x >> 5);
    int lane = threadIdx.x & 31;
    int b = gw >> 7, p = gw & 127;
    const float* __restrict__ x = g_xbuf[0];   // NLAY even -> final in buf 0

    int mnode = b * NPERB + metal_idx[b];
    float xm = x[mnode * HH + lane];

    int s, t;
    if (p < 64) {
        s = loop_edge[(b * 64 + p) * 2 + 0];
        t = loop_edge[(b * 64 + p) * 2 + 1];
    } else {
        int q = p - 64;
        s = loop_pair[(b * 64 + q) * 2 + 0];
        t = loop_pair[(b * 64 + q) * 2 + 1];
    }
    float xs = x[(b * NPERB + s) * HH + lane];
    float xt = x[(b * NPERB + t) * HH + lane];
    float v  = xm * (xs + xt) - xs * xt;
    float fh = xm * f_w[lane];
#pragma unroll
    for (int off = 16; off; off >>= 1) {
        v  += __shfl_xor_sync(0xFFFFFFFFu, v, off);
        fh += __shfl_xor_sync(0xFFFFFFFFu, fh, off);
    }
    if (lane == 0)
        out[b * 128 + p] = (p < 64) ? (v - (fh + f_b[0])) : -v;
}

// ================= launch ====================================================
extern "C" void kernel_launch(void* const* d_in, const int* in_sizes, int n_in,
                              void* d_out, int out_size) {
    const int*   x_nodes    = (const int*)d_in[0];
    const int*   edge_index = (const int*)d_in[1];
    const int*   edge_attr  = (const int*)d_in[2];
    const int*   metal_idx  = (const int*)d_in[3];
    const int*   loop_edge  = (const int*)d_in[4];
    const int*   loop_pair  = (const int*)d_in[5];
    const float* node_emb   = (const float*)d_in[6];
    const float* edge_emb   = (const float*)d_in[7];
    const float* lin_w      = (const float*)d_in[8];
    const float* lin_b      = (const float*)d_in[9];
    const float* root_w     = (const float*)d_in[10];
    const float* conv_b     = (const float*)d_in[11];
    const float* f_w        = (const float*)d_in[12];
    const float* f_b        = (const float*)d_in[13];
    float* out = (float*)d_out;

    cudaFuncSetAttribute(k_layer, cudaFuncAttributeMaxDynamicSharedMemorySize, SMEMB);

    k_setup  <<<736, 256>>>(x_nodes, node_emb, lin_w, lin_b, root_w, edge_index);
    k_scan1  <<<64, 256>>>();
    k_scan2  <<<64, 256>>>();
    k_scatter<<<256, 256>>>(edge_index, edge_attr);

    for (int l = 0; l < NLAY; l++) {
        int inb = l & 1;
        k_layer<<<NN / NPB, 256, SMEMB>>>(edge_emb, conv_b, inb, l, (l < NLAY - 1) ? 1 : 0);
    }

    k_final<<<512, 256>>>(metal_idx, loop_edge, loop_pair, f_w, f_b, out);
}